// round 2
// baseline (speedup 1.0000x reference)
#include <cuda_runtime.h>

#define NQ   9216
#define CIN  128
#define CPL  256
#define BATCH 2

// ---------------- scratch (static device allocations, no cudaMalloc) ----------
__device__ float g_k[BATCH*CIN*NQ];
__device__ float g_v[BATCH*CIN*NQ];
__device__ float g_q[BATCH*CIN*NQ];
__device__ float g_att[BATCH*CIN*NQ];
__device__ float g_c1[BATCH*CPL*NQ];
__device__ float g_bn1[BATCH*CPL*NQ];
__device__ float2 g_st1[CPL];
__device__ float2 g_st2[CPL];

__device__ __forceinline__ float fexp2(float x) {
    float y;
    asm("ex2.approx.ftz.f32 %0, %1;" : "=f"(y) : "f"(x));
    return y;
}

// ---------------------------------------------------------------------------
// Generic tiled GEMM:  C[b][og+i][n0+j] = sum_k A[og+i][k] * B(b)[k][n0+j]
// B is a concat of B1 (K1 rows) and B2 (K2 rows), both [b][k][NQ].
// Tile 64x64, 256 threads, 4x4 microtile. K1, K2 multiples of 16.
// ---------------------------------------------------------------------------
__global__ void gemm_cat_kernel(const float* __restrict__ A,
                                const float* __restrict__ B1,
                                const float* __restrict__ B2,
                                float* __restrict__ C,
                                int K1, int K2, int O)
{
    __shared__ float As[16][64];   // As[k][o]
    __shared__ float Bs[16][64];   // Bs[k][n]

    const int b  = blockIdx.z;
    const int og = blockIdx.y * 64;
    const int n0 = blockIdx.x * 64;
    const int tid = threadIdx.x;
    const int tx = tid & 15, ty = tid >> 4;
    const int K = K1 + K2;

    const float* B1b = B1 + (size_t)b * K1 * NQ;
    const float* B2b = B2 ? (B2 + (size_t)b * K2 * NQ) : nullptr;

    float acc[4][4] = {};
    const int ao  = tid & 63, ag = tid >> 6;       // A loader: row ao, k-chunk ag
    const int bk  = tid >> 4, bn4 = (tid & 15) * 4; // B loader

    for (int kk = 0; kk < K; kk += 16) {
        float4 a = *(const float4*)(A + (size_t)(og + ao) * K + kk + 4 * ag);
        As[4*ag+0][ao] = a.x; As[4*ag+1][ao] = a.y;
        As[4*ag+2][ao] = a.z; As[4*ag+3][ao] = a.w;

        const float* src = (kk < K1)
            ? (B1b + (size_t)(kk + bk) * NQ + n0 + bn4)
            : (B2b + (size_t)(kk + bk - K1) * NQ + n0 + bn4);
        *(float4*)&Bs[bk][bn4] = *(const float4*)src;
        __syncthreads();

        #pragma unroll
        for (int k = 0; k < 16; k++) {
            float4 av = *(float4*)&As[k][ty * 4];
            float4 bv = *(float4*)&Bs[k][tx * 4];
            float ar[4] = {av.x, av.y, av.z, av.w};
            float br[4] = {bv.x, bv.y, bv.z, bv.w};
            #pragma unroll
            for (int i = 0; i < 4; i++)
                #pragma unroll
                for (int j = 0; j < 4; j++)
                    acc[i][j] += ar[i] * br[j];
        }
        __syncthreads();
    }

    float* Cb = C + (size_t)b * O * NQ;
    #pragma unroll
    for (int i = 0; i < 4; i++) {
        float4 w = make_float4(acc[i][0], acc[i][1], acc[i][2], acc[i][3]);
        *(float4*)&Cb[(size_t)(og + ty * 4 + i) * NQ + n0 + tx * 4] = w;
    }
}

// ---------------------------------------------------------------------------
// Flash attention: per (batch, 64-query tile); streams 144 key tiles of 64.
// Q,K,V are [b][128][NQ] in global scratch. Output g_att[b][c][q].
// ---------------------------------------------------------------------------
#define VST 132   // Vst row stride (floats), 16B-aligned rows
#define PST 65    // Ps row stride

__global__ void flash_kernel()
{
    extern __shared__ float sm[];
    float* Qs  = sm;               // [128][64]  Qs[c*64+q]
    float* Ks  = Qs + 128 * 64;    // [128][64]  Ks[c*64+j]
    float* Vst = Ks + 128 * 64;    // [64][VST]  Vst[m*VST+c]
    float* Ps  = Vst + 64 * VST;   // [64][PST]  Ps[m*PST+q]

    const int b  = blockIdx.y;
    const int q0 = blockIdx.x * 64;
    const int tid = threadIdx.x;
    const int tx = tid & 15, ty = tid >> 4;

    const float* qp = g_q + (size_t)b * CIN * NQ;
    const float* kp = g_k + (size_t)b * CIN * NQ;
    const float* vp = g_v + (size_t)b * CIN * NQ;

    // fold softmax scale (c^-0.5) and log2(e) into Q
    const float qscale = 0.08838834764831845f * 1.4426950408889634f;

    for (int i = tid; i < 128 * 16; i += 256) {
        int c = i >> 4, q4 = (i & 15) * 4;
        float4 t = *(const float4*)(qp + (size_t)c * NQ + q0 + q4);
        Qs[c*64+q4+0] = t.x * qscale; Qs[c*64+q4+1] = t.y * qscale;
        Qs[c*64+q4+2] = t.z * qscale; Qs[c*64+q4+3] = t.w * qscale;
    }

    float m_i[4], l_i[4], O[4][8];
    #pragma unroll
    for (int r = 0; r < 4; r++) {
        m_i[r] = -1e30f; l_i[r] = 0.f;
        #pragma unroll
        for (int u = 0; u < 8; u++) O[r][u] = 0.f;
    }

    for (int kt = 0; kt < NQ / 64; kt++) {
        const int k0 = kt * 64;
        __syncthreads();   // prev PV done reading Ps/Vst; Q ready on iter 0

        // K tile (coalesced)
        for (int i = tid; i < 128 * 16; i += 256) {
            int c = i >> 4, j4 = (i & 15) * 4;
            *(float4*)&Ks[c*64+j4] = *(const float4*)(kp + (size_t)c * NQ + k0 + j4);
        }
        // V tile, transposed into Vst[m][c] (conflict-free stores)
        for (int i = tid; i < 2048; i += 256) {
            int c = i & 127, m4 = (i >> 7) * 4;
            float4 t = *(const float4*)(vp + (size_t)c * NQ + k0 + m4);
            Vst[(m4+0)*VST+c] = t.x; Vst[(m4+1)*VST+c] = t.y;
            Vst[(m4+2)*VST+c] = t.z; Vst[(m4+3)*VST+c] = t.w;
        }
        __syncthreads();

        // S = (Q*scale)^T K  over c=128
        float acc[4][4] = {};
        #pragma unroll 4
        for (int c = 0; c < 128; c++) {
            float4 av = *(float4*)&Qs[c*64 + ty*4];
            float4 bv = *(float4*)&Ks[c*64 + tx*4];
            float ar[4] = {av.x, av.y, av.z, av.w};
            float br[4] = {bv.x, bv.y, bv.z, bv.w};
            #pragma unroll
            for (int i = 0; i < 4; i++)
                #pragma unroll
                for (int j = 0; j < 4; j++)
                    acc[i][j] += ar[i] * br[j];
        }

        // online softmax (base-2); row spread across tx = lane bits 0..3
        #pragma unroll
        for (int r = 0; r < 4; r++) {
            float mx = fmaxf(fmaxf(acc[r][0], acc[r][1]), fmaxf(acc[r][2], acc[r][3]));
            #pragma unroll
            for (int o = 8; o; o >>= 1) mx = fmaxf(mx, __shfl_xor_sync(0xffffffffu, mx, o));
            float mn = fmaxf(m_i[r], mx);
            float corr = fexp2(m_i[r] - mn);
            m_i[r] = mn;
            float s = 0.f;
            #pragma unroll
            for (int j = 0; j < 4; j++) {
                float p = fexp2(acc[r][j] - mn);
                Ps[(tx*4 + j) * PST + ty*4 + r] = p;
                s += p;
            }
            #pragma unroll
            for (int o = 8; o; o >>= 1) s += __shfl_xor_sync(0xffffffffu, s, o);
            l_i[r] = l_i[r] * corr + s;
            #pragma unroll
            for (int u = 0; u < 8; u++) O[r][u] *= corr;
        }
        __syncthreads();

        // O += P @ V^T  (outer product over m)
        #pragma unroll 2
        for (int m = 0; m < 64; m++) {
            float4 va = *(float4*)&Vst[m*VST + tx*4];
            float4 vb = *(float4*)&Vst[m*VST + 64 + tx*4];
            #pragma unroll
            for (int r = 0; r < 4; r++) {
                float p = Ps[m*PST + ty*4 + r];
                O[r][0] += p * va.x; O[r][1] += p * va.y;
                O[r][2] += p * va.z; O[r][3] += p * va.w;
                O[r][4] += p * vb.x; O[r][5] += p * vb.y;
                O[r][6] += p * vb.z; O[r][7] += p * vb.w;
            }
        }
    }

    float* op = g_att + (size_t)b * CIN * NQ;
    float inv[4];
    #pragma unroll
    for (int r = 0; r < 4; r++) inv[r] = 1.f / l_i[r];
    #pragma unroll
    for (int u = 0; u < 2; u++)
        #pragma unroll
        for (int v = 0; v < 4; v++) {
            int c = u * 64 + tx * 4 + v;
            float4 w;
            w.x = O[0][u*4+v] * inv[0]; w.y = O[1][u*4+v] * inv[1];
            w.z = O[2][u*4+v] * inv[2]; w.w = O[3][u*4+v] * inv[3];
            *(float4*)&op[(size_t)c * NQ + q0 + ty * 4] = w;
        }
}

// ---------------------------------------------------------------------------
// Per-channel batchnorm statistics over (b, h, w): deterministic tree reduce.
// ---------------------------------------------------------------------------
__global__ void stats_kernel(const float* __restrict__ buf, float2* __restrict__ st, int C)
{
    const int ch = blockIdx.x, tid = threadIdx.x;
    float s1 = 0.f, s2 = 0.f;
    for (int b = 0; b < BATCH; b++) {
        const float* p = buf + ((size_t)b * C + ch) * NQ;
        for (int n = tid * 4; n < NQ; n += 1024) {
            float4 t = *(const float4*)(p + n);
            s1 += t.x + t.y + t.z + t.w;
            s2 += t.x*t.x + t.y*t.y + t.z*t.z + t.w*t.w;
        }
    }
    __shared__ float sh1[256], sh2[256];
    sh1[tid] = s1; sh2[tid] = s2;
    __syncthreads();
    for (int o = 128; o; o >>= 1) {
        if (tid < o) { sh1[tid] += sh1[tid + o]; sh2[tid] += sh2[tid + o]; }
        __syncthreads();
    }
    if (tid == 0) {
        float invn = 1.f / (float)(BATCH * NQ);
        float mean = sh1[0] * invn;
        float var  = sh2[0] * invn - mean * mean;
        st[ch] = make_float2(mean, rsqrtf(var + 1e-5f));
    }
}

__global__ void bn_relu_kernel(const float* __restrict__ in, float* __restrict__ out,
                               const float2* __restrict__ st,
                               const float* __restrict__ gamma,
                               const float* __restrict__ beta, int C)
{
    size_t idx = (size_t)blockIdx.x * blockDim.x + threadIdx.x;
    size_t fi = idx * 4;
    int ch = (int)((fi / NQ) % C);
    float2 s = st[ch];
    float g  = gamma[ch] * s.y;
    float bb = beta[ch] - s.x * g;
    float4 t = *(const float4*)(in + fi);
    t.x = fmaxf(t.x * g + bb, 0.f);
    t.y = fmaxf(t.y * g + bb, 0.f);
    t.z = fmaxf(t.z * g + bb, 0.f);
    t.w = fmaxf(t.w * g + bb, 0.f);
    *(float4*)(out + fi) = t;
}

// ---------------------------------------------------------------------------
extern "C" void kernel_launch(void* const* d_in, const int* in_sizes, int n_in,
                              void* d_out, int out_size)
{
    const float* x      = (const float*)d_in[0];
    const float* Wk     = (const float*)d_in[1];
    const float* Wv     = (const float*)d_in[2];
    const float* Wq     = (const float*)d_in[3];
    const float* Wc1    = (const float*)d_in[4];
    const float* gamma1 = (const float*)d_in[5];
    const float* beta1  = (const float*)d_in[6];
    const float* Wout   = (const float*)d_in[7];
    const float* gamma2 = (const float*)d_in[8];
    const float* beta2  = (const float*)d_in[9];
    float* out = (float*)d_out;

    void *pk, *pv, *pq, *patt, *pc1, *pbn1, *pst1, *pst2;
    cudaGetSymbolAddress(&pk,   g_k);
    cudaGetSymbolAddress(&pv,   g_v);
    cudaGetSymbolAddress(&pq,   g_q);
    cudaGetSymbolAddress(&patt, g_att);
    cudaGetSymbolAddress(&pc1,  g_c1);
    cudaGetSymbolAddress(&pbn1, g_bn1);
    cudaGetSymbolAddress(&pst1, g_st1);
    cudaGetSymbolAddress(&pst2, g_st2);

    const dim3 blk(256);

    // QKV projections: [128,256] @ x[b][256][NQ]
    gemm_cat_kernel<<<dim3(NQ/64, 2, BATCH), blk>>>(Wk, x, nullptr, (float*)pk, 256, 0, 128);
    gemm_cat_kernel<<<dim3(NQ/64, 2, BATCH), blk>>>(Wv, x, nullptr, (float*)pv, 256, 0, 128);
    gemm_cat_kernel<<<dim3(NQ/64, 2, BATCH), blk>>>(Wq, x, nullptr, (float*)pq, 256, 0, 128);

    // Flash attention
    const int smem_bytes = (128*64 + 128*64 + 64*VST + 64*PST) * 4;
    cudaFuncSetAttribute((const void*)flash_kernel,
                         cudaFuncAttributeMaxDynamicSharedMemorySize, smem_bytes);
    flash_kernel<<<dim3(NQ/64, BATCH), blk, smem_bytes>>>();

    // conv1 (Wc1 @ att), then BN+ReLU
    gemm_cat_kernel<<<dim3(NQ/64, 4, BATCH), blk>>>(Wc1, (float*)patt, nullptr, (float*)pc1, 128, 0, 256);
    stats_kernel<<<CPL, 256>>>((float*)pc1, (float2*)pst1, CPL);
    bn_relu_kernel<<<(BATCH*CPL*NQ/4)/256, 256>>>((float*)pc1, (float*)pbn1,
                                                  (float2*)pst1, gamma1, beta1, CPL);

    // out conv on concat [x ; bn1], then BN+ReLU in place on d_out
    gemm_cat_kernel<<<dim3(NQ/64, 4, BATCH), blk>>>(Wout, x, (float*)pbn1, out, 256, 256, 256);
    stats_kernel<<<CPL, 256>>>(out, (float2*)pst2, CPL);
    bn_relu_kernel<<<(BATCH*CPL*NQ/4)/256, 256>>>(out, out, (float2*)pst2, gamma2, beta2, CPL);
}

// round 3
// speedup vs baseline: 4.2391x; 4.2391x over previous
#include <cuda_runtime.h>
#include <cstdint>

#define NQ   9216
#define CIN  128
#define CPL  256
#define BATCH 2

// ---------------- scratch (static device allocations, no cudaMalloc) ----------
__device__ float g_k[BATCH*CIN*NQ];
__device__ float g_v[BATCH*CIN*NQ];
__device__ float g_q[BATCH*CIN*NQ];
__device__ float g_att[BATCH*CIN*NQ];
__device__ float g_c1[BATCH*CPL*NQ];
__device__ float g_bn1[BATCH*CPL*NQ];
__device__ float2 g_st1[CPL];
__device__ float2 g_st2[CPL];

__device__ __forceinline__ float fexp2(float x) {
    float y;
    asm("ex2.approx.ftz.f32 %0, %1;" : "=f"(y) : "f"(x));
    return y;
}
__device__ __forceinline__ uint32_t f2tf(float x) {
    uint32_t r;
    asm("cvt.rna.tf32.f32 %0, %1;" : "=r"(r) : "f"(x));
    return r;
}
__device__ __forceinline__ void cpa16(uint32_t dst, const float* src) {
    asm volatile("cp.async.cg.shared.global [%0], [%1], 16;" :: "r"(dst), "l"(src));
}
__device__ __forceinline__ void mma_tf32(float* c,
    uint32_t a0, uint32_t a1, uint32_t a2, uint32_t a3, uint32_t b0, uint32_t b1) {
    asm volatile("mma.sync.aligned.m16n8k8.row.col.f32.tf32.tf32.f32 "
                 "{%0,%1,%2,%3}, {%4,%5,%6,%7}, {%8,%9}, {%0,%1,%2,%3};"
                 : "+f"(c[0]), "+f"(c[1]), "+f"(c[2]), "+f"(c[3])
                 : "r"(a0), "r"(a1), "r"(a2), "r"(a3), "r"(b0), "r"(b1));
}

// ---------------------------------------------------------------------------
// Generic tiled GEMM:  C[b][og+i][n0+j] = sum_k A[og+i][k] * B(b)[k][n0+j]
// B is a concat of B1 (K1 rows) and B2 (K2 rows), both [b][k][NQ].
// Tile 64x64, 256 threads, 4x4 microtile. tf32out: round result to tf32.
// ---------------------------------------------------------------------------
__global__ void gemm_cat_kernel(const float* __restrict__ A,
                                const float* __restrict__ B1,
                                const float* __restrict__ B2,
                                float* __restrict__ C,
                                int K1, int K2, int O, int tf32out)
{
    __shared__ float As[16][64];
    __shared__ float Bs[16][64];

    const int b  = blockIdx.z;
    const int og = blockIdx.y * 64;
    const int n0 = blockIdx.x * 64;
    const int tid = threadIdx.x;
    const int tx = tid & 15, ty = tid >> 4;
    const int K = K1 + K2;

    const float* B1b = B1 + (size_t)b * K1 * NQ;
    const float* B2b = B2 ? (B2 + (size_t)b * K2 * NQ) : nullptr;

    float acc[4][4] = {};
    const int ao  = tid & 63, ag = tid >> 6;
    const int bk  = tid >> 4, bn4 = (tid & 15) * 4;

    for (int kk = 0; kk < K; kk += 16) {
        float4 a = *(const float4*)(A + (size_t)(og + ao) * K + kk + 4 * ag);
        As[4*ag+0][ao] = a.x; As[4*ag+1][ao] = a.y;
        As[4*ag+2][ao] = a.z; As[4*ag+3][ao] = a.w;

        const float* src = (kk < K1)
            ? (B1b + (size_t)(kk + bk) * NQ + n0 + bn4)
            : (B2b + (size_t)(kk + bk - K1) * NQ + n0 + bn4);
        *(float4*)&Bs[bk][bn4] = *(const float4*)src;
        __syncthreads();

        #pragma unroll
        for (int k = 0; k < 16; k++) {
            float4 av = *(float4*)&As[k][ty * 4];
            float4 bv = *(float4*)&Bs[k][tx * 4];
            float ar[4] = {av.x, av.y, av.z, av.w};
            float br[4] = {bv.x, bv.y, bv.z, bv.w};
            #pragma unroll
            for (int i = 0; i < 4; i++)
                #pragma unroll
                for (int j = 0; j < 4; j++)
                    acc[i][j] += ar[i] * br[j];
        }
        __syncthreads();
    }

    float* Cb = C + (size_t)b * O * NQ;
    #pragma unroll
    for (int i = 0; i < 4; i++) {
        float4 w = make_float4(acc[i][0], acc[i][1], acc[i][2], acc[i][3]);
        if (tf32out) {
            w.x = __uint_as_float(f2tf(w.x)); w.y = __uint_as_float(f2tf(w.y));
            w.z = __uint_as_float(f2tf(w.z)); w.w = __uint_as_float(f2tf(w.w));
        }
        *(float4*)&Cb[(size_t)(og + ty * 4 + i) * NQ + n0 + tx * 4] = w;
    }
}

// ---------------------------------------------------------------------------
// Flash attention with tf32 mma.sync. CTA: 128 queries, streams 144 key tiles
// of 64. Q/K/V are [b][128][NQ] fp32 (K,V pre-rounded to tf32 values).
// ---------------------------------------------------------------------------
#define KST  72          // Ks/Vraw row stride (floats), row = 64 keys + pad
#define VPST 264         // Vp row stride (floats): 128 c * 2 + 8 pad
#define QST  136         // Qs row stride
#define KBUF (128*KST)   // 9216 floats per K/V buffer

__global__ void __launch_bounds__(256, 1) flash_mma_kernel()
{
    extern __shared__ float sm[];
    // layout (floats): Kb0[0] Kb1[9216] Vr0[18432] Vr1[27648] Vp[36864..45312]
    // Qs overlays [27648..45056] (Vr1+Vp), used only before the main loop.
    float* Vp = sm + 4 * KBUF;
    float* Qs = sm + 3 * KBUF;
    const uint32_t smb = (uint32_t)__cvta_generic_to_shared(sm);

    const int b  = blockIdx.y;
    const int q0 = blockIdx.x * 128;
    const int tid  = threadIdx.x;
    const int lane = tid & 31, w = tid >> 5;
    const int g = lane >> 2, t = lane & 3;

    const float* qp = g_q + (size_t)b * CIN * NQ;
    const float* kp = g_k + (size_t)b * CIN * NQ;
    const float* vp = g_v + (size_t)b * CIN * NQ;

    // ---- prologue: async-copy Q tile + K/V tile 0 ----
    #pragma unroll
    for (int j = 0; j < 16; j++) {           // Q: 128 rows x 128 floats
        int idx = tid + j * 256;
        int c = idx >> 5, off = (idx & 31) * 4;
        cpa16(smb + (uint32_t)(3*KBUF + c*QST + off) * 4, qp + (size_t)c * NQ + q0 + off);
    }
    #pragma unroll
    for (int j = 0; j < 8; j++) {            // K tile 0: 128 rows x 64 floats
        int idx = tid + j * 256;
        int c = idx >> 4, off = (idx & 15) * 4;
        cpa16(smb + (uint32_t)(c*KST + off) * 4, kp + (size_t)c * NQ + off);
    }
    #pragma unroll
    for (int j = 0; j < 8; j++) {            // V tile 0
        int idx = tid + j * 256;
        int c = idx >> 4, off = (idx & 15) * 4;
        cpa16(smb + (uint32_t)(2*KBUF + c*KST + off) * 4, vp + (size_t)c * NQ + off);
    }
    asm volatile("cp.async.commit_group;");
    asm volatile("cp.async.wait_group 0;");
    __syncthreads();

    // Q A-fragments in registers (tf32), scale folded in
    const float qscale = 0.08838834764831845f * 1.4426950408889634f;
    uint32_t qa[16][4];
    #pragma unroll
    for (int s = 0; s < 16; s++) {
        const float* r0 = Qs + (8*s + t) * QST + 16*w + g;
        const float* r1 = r0 + 4 * QST;
        qa[s][0] = f2tf(r0[0] * qscale);
        qa[s][1] = f2tf(r0[8] * qscale);
        qa[s][2] = f2tf(r1[0] * qscale);
        qa[s][3] = f2tf(r1[8] * qscale);
    }
    __syncthreads();   // Qs region now reusable (Vr1 / Vp)

    float o[16][4];
    #pragma unroll
    for (int n = 0; n < 16; n++) { o[n][0]=0; o[n][1]=0; o[n][2]=0; o[n][3]=0; }
    float m0 = -1e30f, m1 = -1e30f, l0 = 0.f, l1 = 0.f;

    for (int kt = 0; kt < NQ/64; kt++) {
        const int cb = kt & 1, nb = (kt + 1) & 1;
        // prefetch next tile
        if (kt + 1 < NQ/64) {
            const int k0n = (kt + 1) * 64;
            #pragma unroll
            for (int j = 0; j < 8; j++) {
                int idx = tid + j * 256;
                int c = idx >> 4, off = (idx & 15) * 4;
                cpa16(smb + (uint32_t)(nb*KBUF + c*KST + off) * 4,
                      kp + (size_t)c * NQ + k0n + off);
            }
            #pragma unroll
            for (int j = 0; j < 8; j++) {
                int idx = tid + j * 256;
                int c = idx >> 4, off = (idx & 15) * 4;
                cpa16(smb + (uint32_t)((2+nb)*KBUF + c*KST + off) * 4,
                      vp + (size_t)c * NQ + k0n + off);
            }
        }
        asm volatile("cp.async.commit_group;");
        asm volatile("cp.async.wait_group 1;");
        __syncthreads();

        // transpose V tile: Vraw[c][m] -> Vp[m/2][c][2]
        const float* vr = sm + (2 + cb) * KBUF;
        #pragma unroll
        for (int j = 0; j < 8; j++) {
            int idx = tid + j * 256;
            int c = idx & 127, m4 = (idx >> 7) * 4;
            float4 v = *(const float4*)(vr + c * KST + m4);
            int p = m4 >> 1;
            *(float2*)(Vp + (p    ) * VPST + 2*c) = make_float2(v.x, v.y);
            *(float2*)(Vp + (p + 1) * VPST + 2*c) = make_float2(v.z, v.w);
        }
        __syncthreads();

        // ---- S = Q^T K  (per warp: 16q x 64k) ----
        float sc[8][4];
        #pragma unroll
        for (int u = 0; u < 8; u++) { sc[u][0]=0; sc[u][1]=0; sc[u][2]=0; sc[u][3]=0; }
        const float* K = sm + cb * KBUF;
        #pragma unroll
        for (int s = 0; s < 16; s++) {
            const float* kr0 = K + (8*s + t) * KST + g;
            const float* kr1 = kr0 + 4 * KST;
            #pragma unroll
            for (int u = 0; u < 8; u++) {
                uint32_t b0 = __float_as_uint(kr0[8*u]);
                uint32_t b1 = __float_as_uint(kr1[8*u]);
                mma_tf32(sc[u], qa[s][0], qa[s][1], qa[s][2], qa[s][3], b0, b1);
            }
        }

        // ---- online softmax (rows g and g+8; base-2 domain) ----
        float mx0 = -1e30f, mx1 = -1e30f;
        #pragma unroll
        for (int u = 0; u < 8; u++) {
            mx0 = fmaxf(mx0, fmaxf(sc[u][0], sc[u][1]));
            mx1 = fmaxf(mx1, fmaxf(sc[u][2], sc[u][3]));
        }
        mx0 = fmaxf(mx0, __shfl_xor_sync(0xffffffffu, mx0, 1));
        mx0 = fmaxf(mx0, __shfl_xor_sync(0xffffffffu, mx0, 2));
        mx1 = fmaxf(mx1, __shfl_xor_sync(0xffffffffu, mx1, 1));
        mx1 = fmaxf(mx1, __shfl_xor_sync(0xffffffffu, mx1, 2));
        float nm0 = fmaxf(m0, mx0), nm1 = fmaxf(m1, mx1);
        float cr0 = fexp2(m0 - nm0), cr1 = fexp2(m1 - nm1);
        m0 = nm0; m1 = nm1;

        uint32_t pb[8][4];
        float s0 = 0.f, s1 = 0.f;
        #pragma unroll
        for (int u = 0; u < 8; u++) {
            uint32_t p0 = f2tf(fexp2(sc[u][0] - nm0));
            uint32_t p1 = f2tf(fexp2(sc[u][1] - nm0));
            uint32_t p2 = f2tf(fexp2(sc[u][2] - nm1));
            uint32_t p3 = f2tf(fexp2(sc[u][3] - nm1));
            pb[u][0] = p0; pb[u][1] = p1; pb[u][2] = p2; pb[u][3] = p3;
            s0 += __uint_as_float(p0) + __uint_as_float(p1);
            s1 += __uint_as_float(p2) + __uint_as_float(p3);
        }
        s0 += __shfl_xor_sync(0xffffffffu, s0, 1);
        s0 += __shfl_xor_sync(0xffffffffu, s0, 2);
        s1 += __shfl_xor_sync(0xffffffffu, s1, 1);
        s1 += __shfl_xor_sync(0xffffffffu, s1, 2);
        l0 = l0 * cr0 + s0;
        l1 = l1 * cr1 + s1;
        #pragma unroll
        for (int n = 0; n < 16; n++) {
            o[n][0] *= cr0; o[n][1] *= cr0; o[n][2] *= cr1; o[n][3] *= cr1;
        }

        // ---- O += P V^T.  A from S C-frags with m-permutation:
        // k-slot s<4 -> m=8u+2s (regs pb[u][0],pb[u][2]); s>=4 -> m=8u+2s+1
        // B pair (m, m+1) = one LDS.64 from Vp.
        #pragma unroll
        for (int n = 0; n < 16; n++) {
            #pragma unroll
            for (int u = 0; u < 8; u++) {
                float2 bv = *(const float2*)(Vp + (4*u + t) * VPST + (8*n + g) * 2);
                mma_tf32(o[n], pb[u][0], pb[u][2], pb[u][1], pb[u][3],
                         __float_as_uint(bv.x), __float_as_uint(bv.y));
            }
        }
        __syncthreads();   // protect Kb/Vr/Vp before next iteration's writes
    }

    // ---- epilogue: normalize and store O -> g_att[b][c][q] ----
    const float i0 = 1.f / l0, i1 = 1.f / l1;
    float* op = g_att + (size_t)b * CIN * NQ + q0 + 16*w;
    #pragma unroll
    for (int n = 0; n < 16; n++) {
        int c = 8*n + 2*t;
        op[(size_t)(c    ) * NQ + g    ] = o[n][0] * i0;
        op[(size_t)(c + 1) * NQ + g    ] = o[n][1] * i0;
        op[(size_t)(c    ) * NQ + g + 8] = o[n][2] * i1;
        op[(size_t)(c + 1) * NQ + g + 8] = o[n][3] * i1;
    }
}

// ---------------------------------------------------------------------------
// Per-channel batchnorm statistics over (b, h, w): deterministic tree reduce.
// ---------------------------------------------------------------------------
__global__ void stats_kernel(const float* __restrict__ buf, float2* __restrict__ st, int C)
{
    const int ch = blockIdx.x, tid = threadIdx.x;
    float s1 = 0.f, s2 = 0.f;
    for (int b = 0; b < BATCH; b++) {
        const float* p = buf + ((size_t)b * C + ch) * NQ;
        for (int n = tid * 4; n < NQ; n += 1024) {
            float4 t = *(const float4*)(p + n);
            s1 += t.x + t.y + t.z + t.w;
            s2 += t.x*t.x + t.y*t.y + t.z*t.z + t.w*t.w;
        }
    }
    __shared__ float sh1[256], sh2[256];
    sh1[tid] = s1; sh2[tid] = s2;
    __syncthreads();
    for (int o = 128; o; o >>= 1) {
        if (tid < o) { sh1[tid] += sh1[tid + o]; sh2[tid] += sh2[tid + o]; }
        __syncthreads();
    }
    if (tid == 0) {
        float invn = 1.f / (float)(BATCH * NQ);
        float mean = sh1[0] * invn;
        float var  = sh2[0] * invn - mean * mean;
        st[ch] = make_float2(mean, rsqrtf(var + 1e-5f));
    }
}

__global__ void bn_relu_kernel(const float* __restrict__ in, float* __restrict__ out,
                               const float2* __restrict__ st,
                               const float* __restrict__ gamma,
                               const float* __restrict__ beta, int C)
{
    size_t idx = (size_t)blockIdx.x * blockDim.x + threadIdx.x;
    size_t fi = idx * 4;
    int ch = (int)((fi / NQ) % C);
    float2 s = st[ch];
    float g  = gamma[ch] * s.y;
    float bb = beta[ch] - s.x * g;
    float4 t = *(const float4*)(in + fi);
    t.x = fmaxf(t.x * g + bb, 0.f);
    t.y = fmaxf(t.y * g + bb, 0.f);
    t.z = fmaxf(t.z * g + bb, 0.f);
    t.w = fmaxf(t.w * g + bb, 0.f);
    *(float4*)(out + fi) = t;
}

// ---------------------------------------------------------------------------
extern "C" void kernel_launch(void* const* d_in, const int* in_sizes, int n_in,
                              void* d_out, int out_size)
{
    const float* x      = (const float*)d_in[0];
    const float* Wk     = (const float*)d_in[1];
    const float* Wv     = (const float*)d_in[2];
    const float* Wq     = (const float*)d_in[3];
    const float* Wc1    = (const float*)d_in[4];
    const float* gamma1 = (const float*)d_in[5];
    const float* beta1  = (const float*)d_in[6];
    const float* Wout   = (const float*)d_in[7];
    const float* gamma2 = (const float*)d_in[8];
    const float* beta2  = (const float*)d_in[9];
    float* out = (float*)d_out;

    void *pk, *pv, *pq, *patt, *pc1, *pbn1, *pst1, *pst2;
    cudaGetSymbolAddress(&pk,   g_k);
    cudaGetSymbolAddress(&pv,   g_v);
    cudaGetSymbolAddress(&pq,   g_q);
    cudaGetSymbolAddress(&patt, g_att);
    cudaGetSymbolAddress(&pc1,  g_c1);
    cudaGetSymbolAddress(&pbn1, g_bn1);
    cudaGetSymbolAddress(&pst1, g_st1);
    cudaGetSymbolAddress(&pst2, g_st2);

    const dim3 blk(256);

    // QKV projections (K and V rounded to tf32 in-epilogue for the mma kernel)
    gemm_cat_kernel<<<dim3(NQ/64, 2, BATCH), blk>>>(Wk, x, nullptr, (float*)pk, 256, 0, 128, 1);
    gemm_cat_kernel<<<dim3(NQ/64, 2, BATCH), blk>>>(Wv, x, nullptr, (float*)pv, 256, 0, 128, 1);
    gemm_cat_kernel<<<dim3(NQ/64, 2, BATCH), blk>>>(Wq, x, nullptr, (float*)pq, 256, 0, 128, 0);

    // Flash attention (tf32 tensor cores)
    const int smem_bytes = (4*KBUF + 32*VPST) * 4;   // 181248 B
    cudaFuncSetAttribute((const void*)flash_mma_kernel,
                         cudaFuncAttributeMaxDynamicSharedMemorySize, smem_bytes);
    flash_mma_kernel<<<dim3(NQ/128, BATCH), blk, smem_bytes>>>();

    // conv1 (Wc1 @ att), then BN+ReLU
    gemm_cat_kernel<<<dim3(NQ/64, 4, BATCH), blk>>>(Wc1, (float*)patt, nullptr, (float*)pc1, 128, 0, 256, 0);
    stats_kernel<<<CPL, 256>>>((float*)pc1, (float2*)pst1, CPL);
    bn_relu_kernel<<<(BATCH*CPL*NQ/4)/256, 256>>>((float*)pc1, (float*)pbn1,
                                                  (float2*)pst1, gamma1, beta1, CPL);

    // out conv on concat [x ; bn1], then BN+ReLU in place on d_out
    gemm_cat_kernel<<<dim3(NQ/64, 4, BATCH), blk>>>(Wout, x, (float*)pbn1, out, 256, 256, 256, 0);
    stats_kernel<<<CPL, 256>>>(out, (float2*)pst2, CPL);
    bn_relu_kernel<<<(BATCH*CPL*NQ/4)/256, 256>>>(out, out, (float2*)pst2, gamma2, beta2, CPL);
}

// round 4
// speedup vs baseline: 5.9478x; 1.4031x over previous
#include <cuda_runtime.h>
#include <cuda_fp16.h>
#include <cstdint>

#define NQ   9216
#define CIN  128
#define CPL  256
#define BATCH 2

// ---------------- scratch (static device allocations, no cudaMalloc) ----------
__device__ float    g_q[BATCH*CIN*NQ];
__device__ uint32_t g_kh[BATCH*64*NQ];          // half2 (c,c+1) pairs, [b][cpair][n]
__device__ uint32_t g_vh[BATCH*(NQ/2)*CIN];     // half2 (n,n+1) pairs, [b][npair][c]
__device__ float    g_att[BATCH*CIN*NQ];
__device__ float    g_c1[BATCH*CPL*NQ];
__device__ float    g_bn1[BATCH*CPL*NQ];
__device__ float2   g_st1[CPL];
__device__ float2   g_st2[CPL];

__device__ __forceinline__ float fexp2(float x) {
    float y;
    asm("ex2.approx.ftz.f32 %0, %1;" : "=f"(y) : "f"(x));
    return y;
}
__device__ __forceinline__ void cpa16(uint32_t dst, const void* src) {
    asm volatile("cp.async.cg.shared.global [%0], [%1], 16;" :: "r"(dst), "l"(src));
}
__device__ __forceinline__ uint32_t h2u(__half2 h) { return *(uint32_t*)&h; }
__device__ __forceinline__ void mma_h(float* c,
    uint32_t a0, uint32_t a1, uint32_t a2, uint32_t a3, uint32_t b0, uint32_t b1) {
    asm volatile("mma.sync.aligned.m16n8k16.row.col.f32.f16.f16.f32 "
                 "{%0,%1,%2,%3}, {%4,%5,%6,%7}, {%8,%9}, {%0,%1,%2,%3};"
                 : "+f"(c[0]), "+f"(c[1]), "+f"(c[2]), "+f"(c[3])
                 : "r"(a0), "r"(a1), "r"(a2), "r"(a3), "r"(b0), "r"(b1));
}

// ---------------------------------------------------------------------------
// Generic tiled GEMM:  C[b][og+i][n0+j] = sum_k A[og+i][k] * B(b)[k][n0+j]
// B is a concat of B1 (K1 rows) and B2 (K2 rows), both [b][k][NQ].
// Tile 64x64, 256 threads, 4x4 microtile.
// mode 0: fp32 [O][NQ].  mode 1: K fp16-pack [cpair][NQ].  mode 2: V fp16-pack
// [npair][CIN].
// ---------------------------------------------------------------------------
__global__ void gemm_cat_kernel(const float* __restrict__ A,
                                const float* __restrict__ B1,
                                const float* __restrict__ B2,
                                float* __restrict__ C,
                                int K1, int K2, int O, int mode)
{
    __shared__ float As[16][64];
    __shared__ float Bs[16][64];

    const int b  = blockIdx.z;
    const int og = blockIdx.y * 64;
    const int n0 = blockIdx.x * 64;
    const int tid = threadIdx.x;
    const int tx = tid & 15, ty = tid >> 4;
    const int K = K1 + K2;

    const float* B1b = B1 + (size_t)b * K1 * NQ;
    const float* B2b = B2 ? (B2 + (size_t)b * K2 * NQ) : nullptr;

    float acc[4][4] = {};
    const int ao  = tid & 63, ag = tid >> 6;
    const int bk  = tid >> 4, bn4 = (tid & 15) * 4;

    for (int kk = 0; kk < K; kk += 16) {
        float4 a = *(const float4*)(A + (size_t)(og + ao) * K + kk + 4 * ag);
        As[4*ag+0][ao] = a.x; As[4*ag+1][ao] = a.y;
        As[4*ag+2][ao] = a.z; As[4*ag+3][ao] = a.w;

        const float* src = (kk < K1)
            ? (B1b + (size_t)(kk + bk) * NQ + n0 + bn4)
            : (B2b + (size_t)(kk + bk - K1) * NQ + n0 + bn4);
        *(float4*)&Bs[bk][bn4] = *(const float4*)src;
        __syncthreads();

        #pragma unroll
        for (int k = 0; k < 16; k++) {
            float4 av = *(float4*)&As[k][ty * 4];
            float4 bv = *(float4*)&Bs[k][tx * 4];
            float ar[4] = {av.x, av.y, av.z, av.w};
            float br[4] = {bv.x, bv.y, bv.z, bv.w};
            #pragma unroll
            for (int i = 0; i < 4; i++)
                #pragma unroll
                for (int j = 0; j < 4; j++)
                    acc[i][j] += ar[i] * br[j];
        }
        __syncthreads();
    }

    if (mode == 0) {
        float* Cb = C + (size_t)b * O * NQ;
        #pragma unroll
        for (int i = 0; i < 4; i++) {
            float4 w = make_float4(acc[i][0], acc[i][1], acc[i][2], acc[i][3]);
            *(float4*)&Cb[(size_t)(og + ty * 4 + i) * NQ + n0 + tx * 4] = w;
        }
    } else if (mode == 1) {
        // K pack: g_kh[b][p][n] = half2(K[2p][n], K[2p+1][n])
        uint32_t* dst = g_kh + (size_t)b * 64 * NQ;
        int p0 = (og + ty * 4) >> 1;
        int n  = n0 + tx * 4;
        #pragma unroll
        for (int jj = 0; jj < 2; jj++) {
            uint2 v0, v1;
            v0.x = h2u(__floats2half2_rn(acc[0][2*jj],   acc[1][2*jj]));
            v0.y = h2u(__floats2half2_rn(acc[0][2*jj+1], acc[1][2*jj+1]));
            v1.x = h2u(__floats2half2_rn(acc[2][2*jj],   acc[3][2*jj]));
            v1.y = h2u(__floats2half2_rn(acc[2][2*jj+1], acc[3][2*jj+1]));
            *(uint2*)&dst[(size_t)p0       * NQ + n + 2*jj] = v0;
            *(uint2*)&dst[(size_t)(p0 + 1) * NQ + n + 2*jj] = v1;
        }
    } else {
        // V pack: g_vh[b][p][c] = half2(V[c][2p], V[c][2p+1])
        uint32_t* dst = g_vh + (size_t)b * (NQ/2) * CIN;
        int r0 = (n0 + tx * 4) >> 1;
        int c  = og + ty * 4;
        #pragma unroll
        for (int jj = 0; jj < 2; jj++) {
            #pragma unroll
            for (int ii = 0; ii < 2; ii++) {
                uint2 v;
                v.x = h2u(__floats2half2_rn(acc[2*ii][2*jj],   acc[2*ii][2*jj+1]));
                v.y = h2u(__floats2half2_rn(acc[2*ii+1][2*jj], acc[2*ii+1][2*jj+1]));
                *(uint2*)&dst[(size_t)(r0 + jj) * CIN + c + 2*ii] = v;
            }
        }
    }
}

// ---------------------------------------------------------------------------
// Flash attention, fp16 m16n8k16 mma. CTA: 128 queries x 8 warps, 144 key
// tiles of 64. K/V pre-packed fp16; Q fp32 -> fragments in registers.
// ---------------------------------------------------------------------------
#define KSTH 72                 // K smem row stride (half2 words): bank = 8t+g
#define VSTH 136                // V smem row stride (half2 words): bank = 8t+g
#define KWRD (64*KSTH)          // 4608 words per K buffer
#define VWRD (32*VSTH)          // 4352 words per V buffer
#define FSMEM ((2*KWRD + 2*VWRD) * 4)   // 71680 bytes

__global__ void __launch_bounds__(256, 1) flash_h_kernel()
{
    extern __shared__ float sm[];
    uint32_t* smu = (uint32_t*)sm;
    const uint32_t smb = (uint32_t)__cvta_generic_to_shared(sm);

    const int b  = blockIdx.y;
    const int q0 = blockIdx.x * 128;
    const int tid  = threadIdx.x;
    const int lane = tid & 31, w = tid >> 5;
    const int g = lane >> 2, t = lane & 3;

    const float*    qp  = g_q  + (size_t)b * CIN * NQ;
    const uint32_t* khb = g_kh + (size_t)b * 64 * NQ;
    const uint32_t* vhb = g_vh + (size_t)b * (NQ/2) * CIN;

    // ---- stage Q [c][qlocal] fp32, stride 132 (overlays the K/V buffers) ----
    #pragma unroll
    for (int j = 0; j < 16; j++) {
        int idx = tid + j * 256;
        int c = idx >> 5, o4 = (idx & 31) * 4;
        cpa16(smb + (uint32_t)(c * 132 + o4) * 4, qp + (size_t)c * NQ + q0 + o4);
    }
    asm volatile("cp.async.commit_group;");
    asm volatile("cp.async.wait_group 0;");
    __syncthreads();

    // Q A-fragments (fp16), softmax scale & log2e folded in
    const float qs = 0.08838834764831845f * 1.4426950408889634f;
    const int ql = 16 * w + g;
    uint32_t qa[8][4];
    #pragma unroll
    for (int s = 0; s < 8; s++) {
        int c0 = 16 * s + 2 * t;
        qa[s][0] = h2u(__floats2half2_rn(sm[c0*132 + ql]       * qs, sm[(c0+1)*132 + ql]       * qs));
        qa[s][1] = h2u(__floats2half2_rn(sm[c0*132 + ql + 8]   * qs, sm[(c0+1)*132 + ql + 8]   * qs));
        qa[s][2] = h2u(__floats2half2_rn(sm[(c0+8)*132 + ql]   * qs, sm[(c0+9)*132 + ql]       * qs));
        qa[s][3] = h2u(__floats2half2_rn(sm[(c0+8)*132 + ql+8] * qs, sm[(c0+9)*132 + ql + 8]   * qs));
    }
    __syncthreads();   // Q region now reusable as K/V buffers

    // ---- prologue: tile 0 K/V ----
    #pragma unroll
    for (int j = 0; j < 4; j++) {       // K: 64 rows x 64 half2
        int idx = tid + j * 256;
        int r = idx >> 4, ch = (idx & 15) * 4;
        cpa16(smb + (uint32_t)(r * KSTH + ch) * 4, khb + (size_t)r * NQ + ch);
    }
    #pragma unroll
    for (int j = 0; j < 4; j++) {       // V: 32 rows x 128 half2
        int idx = tid + j * 256;
        int r = idx >> 5, ch = (idx & 31) * 4;
        cpa16(smb + (uint32_t)(2*KWRD + r * VSTH + ch) * 4, vhb + (size_t)r * CIN + ch);
    }
    asm volatile("cp.async.commit_group;");

    float o_[16][4];
    #pragma unroll
    for (int n = 0; n < 16; n++) { o_[n][0]=0; o_[n][1]=0; o_[n][2]=0; o_[n][3]=0; }
    float m0 = -1e30f, m1 = -1e30f, l0 = 0.f, l1 = 0.f;

    for (int kt = 0; kt < NQ/64; kt++) {
        const int cb = kt & 1, nb = cb ^ 1;
        if (kt + 1 < NQ/64) {
            const int k0n  = (kt + 1) * 64;
            const int kp0n = (kt + 1) * 32;
            #pragma unroll
            for (int j = 0; j < 4; j++) {
                int idx = tid + j * 256;
                int r = idx >> 4, ch = (idx & 15) * 4;
                cpa16(smb + (uint32_t)(nb*KWRD + r * KSTH + ch) * 4,
                      khb + (size_t)r * NQ + k0n + ch);
            }
            #pragma unroll
            for (int j = 0; j < 4; j++) {
                int idx = tid + j * 256;
                int r = idx >> 5, ch = (idx & 31) * 4;
                cpa16(smb + (uint32_t)(2*KWRD + nb*VWRD + r * VSTH + ch) * 4,
                      vhb + (size_t)(kp0n + r) * CIN + ch);
            }
        }
        asm volatile("cp.async.commit_group;");
        asm volatile("cp.async.wait_group 1;");
        __syncthreads();

        const uint32_t* Kp = smu + cb * KWRD;
        const uint32_t* Vp = smu + 2*KWRD + cb * VWRD;

        // ---- S = Q^T K  (warp: 16q x 64k) ----
        float sc[8][4];
        #pragma unroll
        for (int u = 0; u < 8; u++) { sc[u][0]=0; sc[u][1]=0; sc[u][2]=0; sc[u][3]=0; }
        #pragma unroll
        for (int s = 0; s < 8; s++) {
            const uint32_t* kr0 = Kp + (8*s + t) * KSTH + g;
            const uint32_t* kr1 = kr0 + 4 * KSTH;
            #pragma unroll
            for (int u = 0; u < 8; u++) {
                mma_h(sc[u], qa[s][0], qa[s][1], qa[s][2], qa[s][3],
                      kr0[8*u], kr1[8*u]);
            }
        }

        // ---- online softmax (rows g -> m0/l0, rows g+8 -> m1/l1) ----
        float mx0 = -1e30f, mx1 = -1e30f;
        #pragma unroll
        for (int u = 0; u < 8; u++) {
            mx0 = fmaxf(mx0, fmaxf(sc[u][0], sc[u][1]));
            mx1 = fmaxf(mx1, fmaxf(sc[u][2], sc[u][3]));
        }
        mx0 = fmaxf(mx0, __shfl_xor_sync(0xffffffffu, mx0, 1));
        mx0 = fmaxf(mx0, __shfl_xor_sync(0xffffffffu, mx0, 2));
        mx1 = fmaxf(mx1, __shfl_xor_sync(0xffffffffu, mx1, 1));
        mx1 = fmaxf(mx1, __shfl_xor_sync(0xffffffffu, mx1, 2));
        float nm0 = fmaxf(m0, mx0), nm1 = fmaxf(m1, mx1);
        float cr0 = fexp2(m0 - nm0), cr1 = fexp2(m1 - nm1);
        m0 = nm0; m1 = nm1;

        uint32_t pb[8][2];
        float s0 = 0.f, s1 = 0.f;
        #pragma unroll
        for (int u = 0; u < 8; u++) {
            float e0 = fexp2(sc[u][0] - nm0);
            float e1 = fexp2(sc[u][1] - nm0);
            float e2 = fexp2(sc[u][2] - nm1);
            float e3 = fexp2(sc[u][3] - nm1);
            __half2 h0 = __floats2half2_rn(e0, e1);
            __half2 h1 = __floats2half2_rn(e2, e3);
            pb[u][0] = h2u(h0); pb[u][1] = h2u(h1);
            float2 f0 = __half22float2(h0);
            float2 f1 = __half22float2(h1);
            s0 += f0.x + f0.y;
            s1 += f1.x + f1.y;
        }
        s0 += __shfl_xor_sync(0xffffffffu, s0, 1);
        s0 += __shfl_xor_sync(0xffffffffu, s0, 2);
        s1 += __shfl_xor_sync(0xffffffffu, s1, 1);
        s1 += __shfl_xor_sync(0xffffffffu, s1, 2);
        l0 = l0 * cr0 + s0;
        l1 = l1 * cr1 + s1;
        #pragma unroll
        for (int n = 0; n < 16; n++) {
            o_[n][0] *= cr0; o_[n][1] *= cr0; o_[n][2] *= cr1; o_[n][3] *= cr1;
        }

        // ---- O += P V^T  (P fragments straight from registers) ----
        #pragma unroll
        for (int nb2 = 0; nb2 < 16; nb2++) {
            #pragma unroll
            for (int s = 0; s < 4; s++) {
                uint32_t b0 = Vp[(8*s + t)     * VSTH + 8*nb2 + g];
                uint32_t b1 = Vp[(8*s + 4 + t) * VSTH + 8*nb2 + g];
                mma_h(o_[nb2], pb[2*s][0], pb[2*s][1], pb[2*s+1][0], pb[2*s+1][1],
                      b0, b1);
            }
        }
        __syncthreads();   // all warps done reading cb buffers
    }

    // ---- epilogue: normalize, store O -> g_att[b][c][q] ----
    const float i0 = 1.f / l0, i1 = 1.f / l1;
    float* op = g_att + (size_t)b * CIN * NQ;
    const int qA = q0 + 16*w + g, qB = qA + 8;
    #pragma unroll
    for (int nb2 = 0; nb2 < 16; nb2++) {
        int c = 8*nb2 + 2*t;
        op[(size_t)c       * NQ + qA] = o_[nb2][0] * i0;
        op[(size_t)(c + 1) * NQ + qA] = o_[nb2][1] * i0;
        op[(size_t)c       * NQ + qB] = o_[nb2][2] * i1;
        op[(size_t)(c + 1) * NQ + qB] = o_[nb2][3] * i1;
    }
}

// ---------------------------------------------------------------------------
// Per-channel batchnorm statistics over (b, h, w): deterministic tree reduce.
// ---------------------------------------------------------------------------
__global__ void stats_kernel(const float* __restrict__ buf, float2* __restrict__ st, int C)
{
    const int ch = blockIdx.x, tid = threadIdx.x;
    float s1 = 0.f, s2 = 0.f;
    for (int b = 0; b < BATCH; b++) {
        const float* p = buf + ((size_t)b * C + ch) * NQ;
        for (int n = tid * 4; n < NQ; n += 1024) {
            float4 t = *(const float4*)(p + n);
            s1 += t.x + t.y + t.z + t.w;
            s2 += t.x*t.x + t.y*t.y + t.z*t.z + t.w*t.w;
        }
    }
    __shared__ float sh1[256], sh2[256];
    sh1[tid] = s1; sh2[tid] = s2;
    __syncthreads();
    for (int o = 128; o; o >>= 1) {
        if (tid < o) { sh1[tid] += sh1[tid + o]; sh2[tid] += sh2[tid + o]; }
        __syncthreads();
    }
    if (tid == 0) {
        float invn = 1.f / (float)(BATCH * NQ);
        float mean = sh1[0] * invn;
        float var  = sh2[0] * invn - mean * mean;
        st[ch] = make_float2(mean, rsqrtf(var + 1e-5f));
    }
}

__global__ void bn_relu_kernel(const float* __restrict__ in, float* __restrict__ out,
                               const float2* __restrict__ st,
                               const float* __restrict__ gamma,
                               const float* __restrict__ beta, int C)
{
    size_t idx = (size_t)blockIdx.x * blockDim.x + threadIdx.x;
    size_t fi = idx * 4;
    int ch = (int)((fi / NQ) % C);
    float2 s = st[ch];
    float g  = gamma[ch] * s.y;
    float bb = beta[ch] - s.x * g;
    float4 t = *(const float4*)(in + fi);
    t.x = fmaxf(t.x * g + bb, 0.f);
    t.y = fmaxf(t.y * g + bb, 0.f);
    t.z = fmaxf(t.z * g + bb, 0.f);
    t.w = fmaxf(t.w * g + bb, 0.f);
    *(float4*)(out + fi) = t;
}

// ---------------------------------------------------------------------------
extern "C" void kernel_launch(void* const* d_in, const int* in_sizes, int n_in,
                              void* d_out, int out_size)
{
    const float* x      = (const float*)d_in[0];
    const float* Wk     = (const float*)d_in[1];
    const float* Wv     = (const float*)d_in[2];
    const float* Wq     = (const float*)d_in[3];
    const float* Wc1    = (const float*)d_in[4];
    const float* gamma1 = (const float*)d_in[5];
    const float* beta1  = (const float*)d_in[6];
    const float* Wout   = (const float*)d_in[7];
    const float* gamma2 = (const float*)d_in[8];
    const float* beta2  = (const float*)d_in[9];
    float* out = (float*)d_out;

    void *pq, *patt, *pc1, *pbn1, *pst1, *pst2;
    cudaGetSymbolAddress(&pq,   g_q);
    cudaGetSymbolAddress(&patt, g_att);
    cudaGetSymbolAddress(&pc1,  g_c1);
    cudaGetSymbolAddress(&pbn1, g_bn1);
    cudaGetSymbolAddress(&pst1, g_st1);
    cudaGetSymbolAddress(&pst2, g_st2);

    const dim3 blk(256);

    // QKV projections. K/V write packed fp16 layouts, Q stays fp32.
    gemm_cat_kernel<<<dim3(NQ/64, 2, BATCH), blk>>>(Wk, x, nullptr, nullptr,     256, 0, 128, 1);
    gemm_cat_kernel<<<dim3(NQ/64, 2, BATCH), blk>>>(Wv, x, nullptr, nullptr,     256, 0, 128, 2);
    gemm_cat_kernel<<<dim3(NQ/64, 2, BATCH), blk>>>(Wq, x, nullptr, (float*)pq,  256, 0, 128, 0);

    // Flash attention (fp16 tensor cores)
    cudaFuncSetAttribute((const void*)flash_h_kernel,
                         cudaFuncAttributeMaxDynamicSharedMemorySize, FSMEM);
    flash_h_kernel<<<dim3(NQ/128, BATCH), blk, FSMEM>>>();

    // conv1 (Wc1 @ att), then BN+ReLU
    gemm_cat_kernel<<<dim3(NQ/64, 4, BATCH), blk>>>(Wc1, (float*)patt, nullptr, (float*)pc1, 128, 0, 256, 0);
    stats_kernel<<<CPL, 256>>>((float*)pc1, (float2*)pst1, CPL);
    bn_relu_kernel<<<(BATCH*CPL*NQ/4)/256, 256>>>((float*)pc1, (float*)pbn1,
                                                  (float2*)pst1, gamma1, beta1, CPL);

    // out conv on concat [x ; bn1], then BN+ReLU in place on d_out
    gemm_cat_kernel<<<dim3(NQ/64, 4, BATCH), blk>>>(Wout, x, (float*)pbn1, out, 256, 256, 256, 0);
    stats_kernel<<<CPL, 256>>>(out, (float2*)pst2, CPL);
    bn_relu_kernel<<<(BATCH*CPL*NQ/4)/256, 256>>>(out, out, (float2*)pst2, gamma2, beta2, CPL);
}

// round 5
// speedup vs baseline: 10.7337x; 1.8047x over previous
#include <cuda_runtime.h>
#include <cuda_fp16.h>
#include <cstdint>

#define NQ   9216
#define CIN  128
#define CPL  256
#define BATCH 2

// ---------------- scratch (static device allocations, no cudaMalloc) ----------
__device__ uint32_t g_qh[BATCH*64*NQ];        // half2 (c,c+8 of 16-block), [b][p][n]
__device__ uint32_t g_kh[BATCH*64*NQ];        // same pairing as Q
__device__ uint32_t g_vh[BATCH*(NQ/2)*CIN];   // half2 (n,n+1) pairs, [b][npair][c]
__device__ uint32_t g_att[BATCH*64*NQ];       // attention out, half2 (c,c+1), [b][p][n]
__device__ uint32_t g_xh[BATCH*128*NQ];       // x packed, half2 (c,c+1), [b][p][n]
__device__ uint32_t g_bn1h[BATCH*128*NQ];     // bn1 packed, half2 (c,c+1)
__device__ float    g_c1[BATCH*CPL*NQ];
__device__ uint32_t g_wqkv[384*128];          // rows 0-127 Wq(scaled),128-255 Wk,256-383 Wv
__device__ uint32_t g_wc1[256*64];
__device__ uint32_t g_wout[256*256];
__device__ float2   g_st1[CPL];
__device__ float2   g_st2[CPL];

__device__ __forceinline__ float fexp2(float x) {
    float y;
    asm("ex2.approx.ftz.f32 %0, %1;" : "=f"(y) : "f"(x));
    return y;
}
__device__ __forceinline__ void cpa16(uint32_t dst, const void* src) {
    asm volatile("cp.async.cg.shared.global [%0], [%1], 16;" :: "r"(dst), "l"(src));
}
__device__ __forceinline__ uint32_t h2u(__half2 h) { return *(uint32_t*)&h; }
__device__ __forceinline__ void mma_h(float* c,
    uint32_t a0, uint32_t a1, uint32_t a2, uint32_t a3, uint32_t b0, uint32_t b1) {
    asm volatile("mma.sync.aligned.m16n8k16.row.col.f32.f16.f16.f32 "
                 "{%0,%1,%2,%3}, {%4,%5,%6,%7}, {%8,%9}, {%0,%1,%2,%3};"
                 : "+f"(c[0]), "+f"(c[1]), "+f"(c[2]), "+f"(c[3])
                 : "r"(a0), "r"(a1), "r"(a2), "r"(a3), "r"(b0), "r"(b1));
}

// ---------------------------------------------------------------------------
// Packing kernels
// ---------------------------------------------------------------------------
__global__ void pack_w_kernel(const float* __restrict__ Wk, const float* __restrict__ Wv,
                              const float* __restrict__ Wq, const float* __restrict__ Wc1,
                              const float* __restrict__ Wout)
{
    int idx = blockIdx.x * 256 + threadIdx.x;
    if (idx < 384*128) {
        int r = idx >> 7, kp = idx & 127;
        const float* src; float s = 1.f;
        if (r < 128)      { src = Wq + (size_t)r*256;
                            s = 0.08838834764831845f * 1.4426950408889634f; }
        else if (r < 256) { src = Wk + (size_t)(r-128)*256; }
        else              { src = Wv + (size_t)(r-256)*256; }
        g_wqkv[idx] = h2u(__floats2half2_rn(src[2*kp]*s, src[2*kp+1]*s));
    } else if (idx < 384*128 + 256*64) {
        int i = idx - 384*128; int r = i >> 6, kp = i & 63;
        g_wc1[i] = h2u(__floats2half2_rn(Wc1[(size_t)r*128 + 2*kp],
                                         Wc1[(size_t)r*128 + 2*kp + 1]));
    } else if (idx < 384*128 + 256*64 + 256*256) {
        int i = idx - (384*128 + 256*64); int r = i >> 8, kp = i & 255;
        g_wout[i] = h2u(__floats2half2_rn(Wout[(size_t)r*512 + 2*kp],
                                          Wout[(size_t)r*512 + 2*kp + 1]));
    }
}

__global__ void pack_x_kernel(const float* __restrict__ x)
{
    int idx = blockIdx.x * 256 + threadIdx.x;    // BATCH*128*NQ/4 threads
    int n4 = (idx % (NQ/4)) * 4;
    int p  = (idx / (NQ/4)) % 128;
    int b  = idx / (128*(NQ/4));
    const float* r0 = x + ((size_t)b*256 + 2*p) * NQ + n4;
    const float* r1 = r0 + NQ;
    float4 v0 = *(const float4*)r0, v1 = *(const float4*)r1;
    uint4 o;
    o.x = h2u(__floats2half2_rn(v0.x, v1.x));
    o.y = h2u(__floats2half2_rn(v0.y, v1.y));
    o.z = h2u(__floats2half2_rn(v0.z, v1.z));
    o.w = h2u(__floats2half2_rn(v0.w, v1.w));
    *(uint4*)&g_xh[(size_t)b*128*NQ + (size_t)p*NQ + n4] = o;
}

// ---------------------------------------------------------------------------
// fp16 tensor-core GEMM: C[m][n] = sum_k W[m][k] * X[k][n]
// Wh [Mtot][K/2] u32 kpairs; B = concat(B1 K1 rows, B2) as [b][K/2][NQ] u32.
// CTA: 256 thr, tile 64m x 256n; k-chunks of 32, cp.async double buffered.
// mode 0: fp32 out to Cf (rows m0+..). mode 3: fused QKV epilogues.
// ---------------------------------------------------------------------------
#define XSTR 264
#define WSTR 20

__global__ void __launch_bounds__(256) gemm_h_kernel(
    const uint32_t* __restrict__ Wh,
    const uint32_t* __restrict__ B1,
    const uint32_t* __restrict__ B2,
    float* __restrict__ Cf,
    int K, int K1, int mode)
{
    __shared__ uint32_t Xs[2][16*XSTR];
    __shared__ uint32_t Ws[2][64*WSTR];
    const uint32_t xsb = (uint32_t)__cvta_generic_to_shared(&Xs[0][0]);
    const uint32_t wsb = (uint32_t)__cvta_generic_to_shared(&Ws[0][0]);

    const int b = blockIdx.z;
    const int n0 = blockIdx.x * 256;
    const int y = blockIdx.y;
    const int m0 = y * 64;
    const int tid = threadIdx.x;
    const int lane = tid & 31, w = tid >> 5;
    const int mw = w & 3, nw = w >> 2;
    const int g = lane >> 2, t = lane & 3;
    const int Kh = K >> 1, K1h = K1 >> 1;
    const uint32_t* B1b = B1 + (size_t)b * K1h * NQ;
    const uint32_t* B2b = B2 ? (B2 + (size_t)b * (Kh - K1h) * NQ) : nullptr;
    const int nchunk = Kh / 16;

    // stage chunk 0
    {
        const uint32_t* src = B1b + n0;
        #pragma unroll
        for (int j = 0; j < 4; j++) {
            int idx = tid + j * 256;
            int r = idx >> 6, cu = (idx & 63) * 4;
            cpa16(xsb + (uint32_t)(r*XSTR + cu) * 4, src + (size_t)r * NQ + cu);
        }
        int rw = tid >> 2, cw = (tid & 3) * 4;
        cpa16(wsb + (uint32_t)(rw*WSTR + cw) * 4, Wh + (size_t)(m0 + rw) * Kh + cw);
    }
    asm volatile("cp.async.commit_group;");

    float acc[16][4];
    #pragma unroll
    for (int u = 0; u < 16; u++) { acc[u][0]=0; acc[u][1]=0; acc[u][2]=0; acc[u][3]=0; }

    for (int ch = 0; ch < nchunk; ch++) {
        const int buf = ch & 1;
        if (ch + 1 < nchunk) {
            int kp0 = (ch + 1) * 16;
            const uint32_t* src = (kp0 < K1h) ? (B1b + (size_t)kp0 * NQ + n0)
                                              : (B2b + (size_t)(kp0 - K1h) * NQ + n0);
            #pragma unroll
            for (int j = 0; j < 4; j++) {
                int idx = tid + j * 256;
                int r = idx >> 6, cu = (idx & 63) * 4;
                cpa16(xsb + (uint32_t)((buf^1)*16*XSTR + r*XSTR + cu) * 4,
                      src + (size_t)r * NQ + cu);
            }
            int rw = tid >> 2, cw = (tid & 3) * 4;
            cpa16(wsb + (uint32_t)((buf^1)*64*WSTR + rw*WSTR + cw) * 4,
                  Wh + (size_t)(m0 + rw) * Kh + kp0 + cw);
        }
        asm volatile("cp.async.commit_group;");
        asm volatile("cp.async.wait_group 1;");
        __syncthreads();

        const uint32_t* Xb = &Xs[buf][0];
        const uint32_t* Wb = &Ws[buf][0];
        #pragma unroll
        for (int j = 0; j < 2; j++) {
            uint32_t a0 = Wb[(mw*16+g)*WSTR   + 8*j + t];
            uint32_t a1 = Wb[(mw*16+g+8)*WSTR + 8*j + t];
            uint32_t a2 = Wb[(mw*16+g)*WSTR   + 8*j + 4 + t];
            uint32_t a3 = Wb[(mw*16+g+8)*WSTR + 8*j + 4 + t];
            #pragma unroll
            for (int u = 0; u < 16; u++) {
                uint32_t b0 = Xb[(8*j+t)*XSTR   + nw*128 + 8*u + g];
                uint32_t b1 = Xb[(8*j+4+t)*XSTR + nw*128 + 8*u + g];
                mma_h(acc[u], a0, a1, a2, a3, b0, b1);
            }
        }
        __syncthreads();
    }

    const int nb = n0 + nw*128 + 2*t;
    if (mode == 0) {
        float* Cb = Cf + ((size_t)b*256 + m0 + mw*16 + g) * NQ + nb;
        #pragma unroll
        for (int u = 0; u < 16; u++) {
            *(float2*)&Cb[8*u] = make_float2(acc[u][0], acc[u][1]);
            *(float2*)&Cb[(size_t)8*NQ + 8*u] = make_float2(acc[u][2], acc[u][3]);
        }
    } else {
        if (y < 2) {           // Q -> g_qh, pairs (c, c+8)
            uint32_t* dst = g_qh + (size_t)b*64*NQ + (size_t)(8*(y*4+mw)+g)*NQ + nb;
            #pragma unroll
            for (int u = 0; u < 16; u++) {
                uint2 v;
                v.x = h2u(__floats2half2_rn(acc[u][0], acc[u][2]));
                v.y = h2u(__floats2half2_rn(acc[u][1], acc[u][3]));
                *(uint2*)&dst[8*u] = v;
            }
        } else if (y < 4) {    // K -> g_kh
            uint32_t* dst = g_kh + (size_t)b*64*NQ + (size_t)(8*((y-2)*4+mw)+g)*NQ + nb;
            #pragma unroll
            for (int u = 0; u < 16; u++) {
                uint2 v;
                v.x = h2u(__floats2half2_rn(acc[u][0], acc[u][2]));
                v.y = h2u(__floats2half2_rn(acc[u][1], acc[u][3]));
                *(uint2*)&dst[8*u] = v;
            }
        } else {               // V -> g_vh, pairs (n, n+1)
            uint32_t* dst = g_vh + (size_t)b*(NQ/2)*CIN;
            int c = (y-4)*64 + mw*16 + g;
            int npb = (n0 + nw*128)/2 + t;
            #pragma unroll
            for (int u = 0; u < 16; u++) {
                int np = npb + 4*u;
                dst[(size_t)np*CIN + c]     = h2u(__floats2half2_rn(acc[u][0], acc[u][1]));
                dst[(size_t)np*CIN + c + 8] = h2u(__floats2half2_rn(acc[u][2], acc[u][3]));
            }
        }
    }
}

// ---------------------------------------------------------------------------
// Flash attention, fp16 m16n8k16. CTA: 128 queries x 8 warps, 144 key tiles
// of 64. Q/K/V pre-packed fp16 (Q/K pairs (c,c+8); V pairs (n,n+1)).
// ---------------------------------------------------------------------------
#define KSTH 72
#define VSTH 136
#define KWRD (64*KSTH)
#define VWRD (32*VSTH)
#define FSMEM ((2*KWRD + 2*VWRD) * 4)   // 71680 bytes

__global__ void __launch_bounds__(256, 1) flash_h_kernel()
{
    extern __shared__ float sm[];
    uint32_t* smu = (uint32_t*)sm;
    const uint32_t smb = (uint32_t)__cvta_generic_to_shared(sm);

    const int b  = blockIdx.y;
    const int q0 = blockIdx.x * 128;
    const int tid  = threadIdx.x;
    const int lane = tid & 31, w = tid >> 5;
    const int g = lane >> 2, t = lane & 3;

    const uint32_t* qhb = g_qh + (size_t)b * 64 * NQ;
    const uint32_t* khb = g_kh + (size_t)b * 64 * NQ;
    const uint32_t* vhb = g_vh + (size_t)b * (NQ/2) * CIN;

    // ---- stage Q (64 rows x 128 u32, stride 136; overlays K/V buffers) ----
    #pragma unroll
    for (int j = 0; j < 8; j++) {
        int idx = tid + j * 256;
        int p = idx >> 5, o4 = (idx & 31) * 4;
        cpa16(smb + (uint32_t)(p * 136 + o4) * 4, qhb + (size_t)p * NQ + q0 + o4);
    }
    asm volatile("cp.async.commit_group;");
    asm volatile("cp.async.wait_group 0;");
    __syncthreads();

    const int ql = 16 * w + g;
    uint32_t qa[8][4];
    #pragma unroll
    for (int s = 0; s < 8; s++) {
        qa[s][0] = smu[(8*s + t)     * 136 + ql];
        qa[s][1] = smu[(8*s + t)     * 136 + ql + 8];
        qa[s][2] = smu[(8*s + 4 + t) * 136 + ql];
        qa[s][3] = smu[(8*s + 4 + t) * 136 + ql + 8];
    }
    __syncthreads();   // Q region now reusable as K/V buffers

    // ---- prologue: tile 0 K/V ----
    #pragma unroll
    for (int j = 0; j < 4; j++) {
        int idx = tid + j * 256;
        int r = idx >> 4, ch = (idx & 15) * 4;
        cpa16(smb + (uint32_t)(r * KSTH + ch) * 4, khb + (size_t)r * NQ + ch);
    }
    #pragma unroll
    for (int j = 0; j < 4; j++) {
        int idx = tid + j * 256;
        int r = idx >> 5, ch = (idx & 31) * 4;
        cpa16(smb + (uint32_t)(2*KWRD + r * VSTH + ch) * 4, vhb + (size_t)r * CIN + ch);
    }
    asm volatile("cp.async.commit_group;");

    float o_[16][4];
    #pragma unroll
    for (int n = 0; n < 16; n++) { o_[n][0]=0; o_[n][1]=0; o_[n][2]=0; o_[n][3]=0; }
    float m0 = -1e30f, m1 = -1e30f, l0 = 0.f, l1 = 0.f;

    for (int kt = 0; kt < NQ/64; kt++) {
        const int cb = kt & 1, nb = cb ^ 1;
        if (kt + 1 < NQ/64) {
            const int k0n  = (kt + 1) * 64;
            const int kp0n = (kt + 1) * 32;
            #pragma unroll
            for (int j = 0; j < 4; j++) {
                int idx = tid + j * 256;
                int r = idx >> 4, ch = (idx & 15) * 4;
                cpa16(smb + (uint32_t)(nb*KWRD + r * KSTH + ch) * 4,
                      khb + (size_t)r * NQ + k0n + ch);
            }
            #pragma unroll
            for (int j = 0; j < 4; j++) {
                int idx = tid + j * 256;
                int r = idx >> 5, ch = (idx & 31) * 4;
                cpa16(smb + (uint32_t)(2*KWRD + nb*VWRD + r * VSTH + ch) * 4,
                      vhb + (size_t)(kp0n + r) * CIN + ch);
            }
        }
        asm volatile("cp.async.commit_group;");
        asm volatile("cp.async.wait_group 1;");
        __syncthreads();

        const uint32_t* Kp = smu + cb * KWRD;
        const uint32_t* Vp = smu + 2*KWRD + cb * VWRD;

        // ---- S = Q^T K ----
        float sc[8][4];
        #pragma unroll
        for (int u = 0; u < 8; u++) { sc[u][0]=0; sc[u][1]=0; sc[u][2]=0; sc[u][3]=0; }
        #pragma unroll
        for (int s = 0; s < 8; s++) {
            const uint32_t* kr0 = Kp + (8*s + t) * KSTH + g;
            const uint32_t* kr1 = kr0 + 4 * KSTH;
            #pragma unroll
            for (int u = 0; u < 8; u++) {
                mma_h(sc[u], qa[s][0], qa[s][1], qa[s][2], qa[s][3],
                      kr0[8*u], kr1[8*u]);
            }
        }

        // ---- online softmax ----
        float mx0 = -1e30f, mx1 = -1e30f;
        #pragma unroll
        for (int u = 0; u < 8; u++) {
            mx0 = fmaxf(mx0, fmaxf(sc[u][0], sc[u][1]));
            mx1 = fmaxf(mx1, fmaxf(sc[u][2], sc[u][3]));
        }
        mx0 = fmaxf(mx0, __shfl_xor_sync(0xffffffffu, mx0, 1));
        mx0 = fmaxf(mx0, __shfl_xor_sync(0xffffffffu, mx0, 2));
        mx1 = fmaxf(mx1, __shfl_xor_sync(0xffffffffu, mx1, 1));
        mx1 = fmaxf(mx1, __shfl_xor_sync(0xffffffffu, mx1, 2));
        float nm0 = fmaxf(m0, mx0), nm1 = fmaxf(m1, mx1);
        float cr0 = fexp2(m0 - nm0), cr1 = fexp2(m1 - nm1);
        m0 = nm0; m1 = nm1;

        uint32_t pb[8][2];
        float s0 = 0.f, s1 = 0.f;
        #pragma unroll
        for (int u = 0; u < 8; u++) {
            float e0 = fexp2(sc[u][0] - nm0);
            float e1 = fexp2(sc[u][1] - nm0);
            float e2 = fexp2(sc[u][2] - nm1);
            float e3 = fexp2(sc[u][3] - nm1);
            __half2 h0 = __floats2half2_rn(e0, e1);
            __half2 h1 = __floats2half2_rn(e2, e3);
            pb[u][0] = h2u(h0); pb[u][1] = h2u(h1);
            float2 f0 = __half22float2(h0);
            float2 f1 = __half22float2(h1);
            s0 += f0.x + f0.y;
            s1 += f1.x + f1.y;
        }
        s0 += __shfl_xor_sync(0xffffffffu, s0, 1);
        s0 += __shfl_xor_sync(0xffffffffu, s0, 2);
        s1 += __shfl_xor_sync(0xffffffffu, s1, 1);
        s1 += __shfl_xor_sync(0xffffffffu, s1, 2);
        l0 = l0 * cr0 + s0;
        l1 = l1 * cr1 + s1;
        #pragma unroll
        for (int n = 0; n < 16; n++) {
            o_[n][0] *= cr0; o_[n][1] *= cr0; o_[n][2] *= cr1; o_[n][3] *= cr1;
        }

        // ---- O += P V^T ----
        #pragma unroll
        for (int nb2 = 0; nb2 < 16; nb2++) {
            #pragma unroll
            for (int s = 0; s < 4; s++) {
                uint32_t b0 = Vp[(8*s + t)     * VSTH + 8*nb2 + g];
                uint32_t b1 = Vp[(8*s + 4 + t) * VSTH + 8*nb2 + g];
                mma_h(o_[nb2], pb[2*s][0], pb[2*s][1], pb[2*s+1][0], pb[2*s+1][1],
                      b0, b1);
            }
        }
        __syncthreads();
    }

    // ---- epilogue: normalize, pack (c,c+1) half2, store to g_att ----
    const float i0 = 1.f / l0, i1 = 1.f / l1;
    uint32_t* op = g_att + (size_t)b * 64 * NQ;
    const int qA = q0 + 16*w + g, qB = qA + 8;
    #pragma unroll
    for (int nb2 = 0; nb2 < 16; nb2++) {
        int p = 4*nb2 + t;
        op[(size_t)p * NQ + qA] = h2u(__floats2half2_rn(o_[nb2][0]*i0, o_[nb2][1]*i0));
        op[(size_t)p * NQ + qB] = h2u(__floats2half2_rn(o_[nb2][2]*i1, o_[nb2][3]*i1));
    }
}

// ---------------------------------------------------------------------------
// BN statistics + BN/ReLU epilogues
// ---------------------------------------------------------------------------
__global__ void stats_kernel(const float* __restrict__ buf, float2* __restrict__ st, int C)
{
    const int ch = blockIdx.x, tid = threadIdx.x;
    float s1 = 0.f, s2 = 0.f;
    for (int b = 0; b < BATCH; b++) {
        const float* p = buf + ((size_t)b * C + ch) * NQ;
        for (int n = tid * 4; n < NQ; n += 1024) {
            float4 t = *(const float4*)(p + n);
            s1 += t.x + t.y + t.z + t.w;
            s2 += t.x*t.x + t.y*t.y + t.z*t.z + t.w*t.w;
        }
    }
    __shared__ float sh1[256], sh2[256];
    sh1[tid] = s1; sh2[tid] = s2;
    __syncthreads();
    for (int o = 128; o; o >>= 1) {
        if (tid < o) { sh1[tid] += sh1[tid + o]; sh2[tid] += sh2[tid + o]; }
        __syncthreads();
    }
    if (tid == 0) {
        float invn = 1.f / (float)(BATCH * NQ);
        float mean = sh1[0] * invn;
        float var  = sh2[0] * invn - mean * mean;
        st[ch] = make_float2(mean, rsqrtf(var + 1e-5f));
    }
}

// BN+ReLU on g_c1, output packed half2 (c,c+1) pairs into g_bn1h
__global__ void bn_relu_pack_kernel(const float* __restrict__ in,
                                    const float2* __restrict__ st,
                                    const float* __restrict__ gamma,
                                    const float* __restrict__ beta)
{
    int idx = blockIdx.x * 256 + threadIdx.x;     // BATCH*128*NQ/4
    int n4 = (idx % (NQ/4)) * 4;
    int p  = (idx / (NQ/4)) % 128;
    int b  = idx / (128*(NQ/4));
    int c0 = 2*p, c1 = 2*p + 1;
    float2 sA = st[c0], sB = st[c1];
    float gA = gamma[c0] * sA.y, bA = beta[c0] - sA.x * gA;
    float gB = gamma[c1] * sB.y, bB = beta[c1] - sB.x * gB;
    const float* r0 = in + ((size_t)b*256 + c0) * NQ + n4;
    const float* r1 = r0 + NQ;
    float4 v0 = *(const float4*)r0, v1 = *(const float4*)r1;
    v0.x = fmaxf(v0.x*gA + bA, 0.f); v0.y = fmaxf(v0.y*gA + bA, 0.f);
    v0.z = fmaxf(v0.z*gA + bA, 0.f); v0.w = fmaxf(v0.w*gA + bA, 0.f);
    v1.x = fmaxf(v1.x*gB + bB, 0.f); v1.y = fmaxf(v1.y*gB + bB, 0.f);
    v1.z = fmaxf(v1.z*gB + bB, 0.f); v1.w = fmaxf(v1.w*gB + bB, 0.f);
    uint4 o;
    o.x = h2u(__floats2half2_rn(v0.x, v1.x));
    o.y = h2u(__floats2half2_rn(v0.y, v1.y));
    o.z = h2u(__floats2half2_rn(v0.z, v1.z));
    o.w = h2u(__floats2half2_rn(v0.w, v1.w));
    *(uint4*)&g_bn1h[(size_t)b*128*NQ + (size_t)p*NQ + n4] = o;
}

__global__ void bn_relu_kernel(const float* __restrict__ in, float* __restrict__ out,
                               const float2* __restrict__ st,
                               const float* __restrict__ gamma,
                               const float* __restrict__ beta, int C)
{
    size_t idx = (size_t)blockIdx.x * blockDim.x + threadIdx.x;
    size_t fi = idx * 4;
    int ch = (int)((fi / NQ) % C);
    float2 s = st[ch];
    float g  = gamma[ch] * s.y;
    float bb = beta[ch] - s.x * g;
    float4 t = *(const float4*)(in + fi);
    t.x = fmaxf(t.x * g + bb, 0.f);
    t.y = fmaxf(t.y * g + bb, 0.f);
    t.z = fmaxf(t.z * g + bb, 0.f);
    t.w = fmaxf(t.w * g + bb, 0.f);
    *(float4*)(out + fi) = t;
}

// ---------------------------------------------------------------------------
extern "C" void kernel_launch(void* const* d_in, const int* in_sizes, int n_in,
                              void* d_out, int out_size)
{
    const float* x      = (const float*)d_in[0];
    const float* Wk     = (const float*)d_in[1];
    const float* Wv     = (const float*)d_in[2];
    const float* Wq     = (const float*)d_in[3];
    const float* Wc1    = (const float*)d_in[4];
    const float* gamma1 = (const float*)d_in[5];
    const float* beta1  = (const float*)d_in[6];
    const float* Wout   = (const float*)d_in[7];
    const float* gamma2 = (const float*)d_in[8];
    const float* beta2  = (const float*)d_in[9];
    float* out = (float*)d_out;

    void *pwqkv, *pwc1, *pwout, *pxh, *patt, *pbn1h, *pc1, *pst1, *pst2;
    cudaGetSymbolAddress(&pwqkv, g_wqkv);
    cudaGetSymbolAddress(&pwc1,  g_wc1);
    cudaGetSymbolAddress(&pwout, g_wout);
    cudaGetSymbolAddress(&pxh,   g_xh);
    cudaGetSymbolAddress(&patt,  g_att);
    cudaGetSymbolAddress(&pbn1h, g_bn1h);
    cudaGetSymbolAddress(&pc1,   g_c1);
    cudaGetSymbolAddress(&pst1,  g_st1);
    cudaGetSymbolAddress(&pst2,  g_st2);

    // pack weights + x to fp16
    pack_w_kernel<<<512, 256>>>(Wk, Wv, Wq, Wc1, Wout);
    pack_x_kernel<<<BATCH*128*(NQ/4)/256, 256>>>(x);

    // fused QKV projection (tensor cores) -> packed q/k/v
    gemm_h_kernel<<<dim3(NQ/256, 6, BATCH), 256>>>(
        (const uint32_t*)pwqkv, (const uint32_t*)pxh, nullptr, nullptr, 256, 256, 3);

    // flash attention
    cudaFuncSetAttribute((const void*)flash_h_kernel,
                         cudaFuncAttributeMaxDynamicSharedMemorySize, FSMEM);
    flash_h_kernel<<<dim3(NQ/128, BATCH), 256, FSMEM>>>();

    // conv1: Wc1 @ att -> g_c1 (fp32), then BN stats + BN/ReLU (packed out)
    gemm_h_kernel<<<dim3(NQ/256, 4, BATCH), 256>>>(
        (const uint32_t*)pwc1, (const uint32_t*)patt, nullptr, (float*)pc1, 128, 128, 0);
    stats_kernel<<<CPL, 256>>>((float*)pc1, (float2*)pst1, CPL);
    bn_relu_pack_kernel<<<BATCH*128*(NQ/4)/256, 256>>>((float*)pc1, (float2*)pst1,
                                                       gamma1, beta1);

    // out conv on concat [xh ; bn1h] -> d_out, then BN stats + BN/ReLU in place
    gemm_h_kernel<<<dim3(NQ/256, 4, BATCH), 256>>>(
        (const uint32_t*)pwout, (const uint32_t*)pxh, (const uint32_t*)pbn1h,
        out, 512, 256, 0);
    stats_kernel<<<CPL, 256>>>(out, (float2*)pst2, CPL);
    bn_relu_kernel<<<(BATCH*CPL*NQ/4)/256, 256>>>(out, out, (float2*)pst2,
                                                  gamma2, beta2, CPL);
}